// round 5
// baseline (speedup 1.0000x reference)
#include <cuda_runtime.h>
#include <cuda_bf16.h>

// Wasserstein CT cost-matrix mean.
// Algebraic identity: mean(matrix) = 2(C-1)/C^2 * mean(|ct|).
// Per pixel, sum_{c,l} |1{t==l} - 1{q==c}| = 2(C-1) regardless of t,q.
// So only ct matters: result = 2(C-1)/(C^2*N) * sum(|ct|).
//
// Single fused kernel, 128 CTAs x 128 threads (4 warps/block -> shallow
// barrier + 2-round stage-2 reduce). Block partials -> acq_rel ticket ->
// last block warp0 final reduce. Deterministic: fixed partial slots,
// fixed-order tree, ticket reset by the last block per call.

#define RED_BLOCKS 128
#define RED_THREADS 128
#define UNROLL 4

__device__ float4 g_partials4[RED_BLOCKS / 4];   // viewed as float[RED_BLOCKS]
__device__ unsigned int g_ticket;                 // zero-init; reset each call

__device__ __forceinline__ float warp_reduce_sum(float v) {
    #pragma unroll
    for (int off = 16; off > 0; off >>= 1)
        v += __shfl_xor_sync(0xFFFFFFFFu, v, off);
    return v;
}

__global__ void __launch_bounds__(RED_THREADS)
abs_mean_fused(const float* __restrict__ ct, int n, float scale,
               float* __restrict__ out) {
    __shared__ float s_warp[RED_THREADS / 32];    // 4 warp sums
    __shared__ bool s_is_last;

    const int tid = threadIdx.x;
    const int gtid = blockIdx.x * RED_THREADS + tid;
    const int nthreads = RED_BLOCKS * RED_THREADS;   // 16384

    const int nv4 = n >> 2;
    const float4* __restrict__ ct4 = reinterpret_cast<const float4*>(ct);

    float acc = 0.0f;

    // Fast path: n = 512*512 -> each thread exactly 4 float4 loads, all
    // issued back-to-back (front-batched MLP) before any consume.
    if (nv4 == nthreads * UNROLL) {
        float4 v[UNROLL];
        #pragma unroll
        for (int u = 0; u < UNROLL; u++)
            v[u] = ct4[gtid + u * nthreads];
        #pragma unroll
        for (int u = 0; u < UNROLL; u++)
            acc += fabsf(v[u].x) + fabsf(v[u].y) + fabsf(v[u].z) + fabsf(v[u].w);
    } else {
        // Robust grid-stride path for other sizes.
        for (int i = gtid; i < nv4; i += nthreads) {
            float4 v = ct4[i];
            acc += fabsf(v.x) + fabsf(v.y) + fabsf(v.z) + fabsf(v.w);
        }
        if (gtid == 0) {
            for (int i = nv4 << 2; i < n; i++) acc += fabsf(ct[i]);
        }
    }

    // In-warp reduction (5 rounds).
    acc = warp_reduce_sum(acc);
    if ((tid & 31) == 0) s_warp[tid >> 5] = acc;
    __syncthreads();

    // Stage 2: only 4 warp sums -> 2 shfl rounds in lanes 0..3.
    if (tid < 32) {
        float v = (tid < RED_THREADS / 32) ? s_warp[tid] : 0.0f;
        v += __shfl_xor_sync(0xFFFFFFFFu, v, 2);
        v += __shfl_xor_sync(0xFFFFFFFFu, v, 1);
        if (tid == 0) {
            reinterpret_cast<float*>(g_partials4)[blockIdx.x] = v;
            // acq_rel RMW: release orders the partial store; the winning
            // (last) increment's acquire makes ALL partials visible.
            unsigned int t;
            asm volatile("atom.add.acq_rel.gpu.u32 %0, [%1], %2;"
                         : "=r"(t)
                         : "l"(&g_ticket), "r"(1u)
                         : "memory");
            s_is_last = (t == (unsigned int)(RED_BLOCKS - 1));
        }
    }
    __syncthreads();

    // Last block, warp 0 only: 128 partials as 32x float4 (one coalesced
    // 512B load), 3 adds/lane, one warp reduce, scalar store.
    if (s_is_last && tid < 32) {
        float4 p = g_partials4[tid];
        float v = (p.x + p.y) + (p.z + p.w);
        v = warp_reduce_sum(v);
        if (tid == 0) {
            out[0] = v * scale;
            g_ticket = 0u;  // restore for next graph replay
        }
    }
}

extern "C" void kernel_launch(void* const* d_in, const int* in_sizes, int n_in,
                              void* d_out, int out_size) {
    // Inputs (metadata order): pred_stage1 [1,C,H,W] f32, ct [1,H,W] f32,
    // target [1,1,H,W] i64. Only ct is needed (see identity above).
    const float* ct = (const float*)d_in[1];
    const int n = in_sizes[1];                      // H*W
    const int C = (n > 0) ? (in_sizes[0] / n) : 1;  // class count from pred size

    const double scale_d = (2.0 * (double)(C - 1)) /
                           ((double)C * (double)C * (double)n);
    const float scale = (float)scale_d;

    abs_mean_fused<<<RED_BLOCKS, RED_THREADS>>>(ct, n, scale, (float*)d_out);
}

// round 6
// speedup vs baseline: 1.1082x; 1.1082x over previous
#include <cuda_runtime.h>
#include <cuda_bf16.h>

// Wasserstein CT cost-matrix mean.
// Algebraic identity: mean(matrix) = 2(C-1)/C^2 * mean(|ct|).
// Per pixel, sum_{c,l} |1{t==l} - 1{q==c}| = 2(C-1) regardless of t,q.
// So only ct matters: result = 2(C-1)/(C^2*N) * sum(|ct|).
//
// Single fused kernel, 128 CTAs x 256 threads (R4 measured-best load shape).
// Tail: ONE u64 fixed-point atomic per block carries both the partial sum
// (bits [8:64), 2^-24 units) and the arrival count (bits [0:8)). Integer
// adds commute -> bit-deterministic result independent of arrival order.
// The last block's thread 0 gets the complete sum from the atomic return,
// writes the scalar, and resets the accumulator for the next graph replay.

#define RED_BLOCKS 128
#define RED_THREADS 256
#define UNROLL 2
#define FIX_SCALE 16777216.0f          // 2^24
#define FIX_INV   (1.0f / 16777216.0f)

__device__ unsigned long long g_acc;   // zero-init; reset by last block

__device__ __forceinline__ float warp_reduce_sum(float v) {
    #pragma unroll
    for (int off = 16; off > 0; off >>= 1)
        v += __shfl_xor_sync(0xFFFFFFFFu, v, off);
    return v;
}

__global__ void __launch_bounds__(RED_THREADS)
abs_mean_fused(const float* __restrict__ ct, int n, float scale,
               float* __restrict__ out) {
    __shared__ float s_warp[RED_THREADS / 32];

    const int tid = threadIdx.x;
    const int gtid = blockIdx.x * RED_THREADS + tid;
    const int nthreads = RED_BLOCKS * RED_THREADS;   // 32768

    const int nv4 = n >> 2;
    const float4* __restrict__ ct4 = reinterpret_cast<const float4*>(ct);

    float acc = 0.0f;

    // Fast path: n = 512*512 -> exactly 2 front-batched float4 loads/thread.
    if (nv4 == nthreads * UNROLL) {
        float4 v0 = ct4[gtid];
        float4 v1 = ct4[gtid + nthreads];
        acc  = fabsf(v0.x) + fabsf(v0.y) + fabsf(v0.z) + fabsf(v0.w);
        acc += fabsf(v1.x) + fabsf(v1.y) + fabsf(v1.z) + fabsf(v1.w);
    } else {
        // Robust grid-stride path for other sizes.
        for (int i = gtid; i < nv4; i += nthreads) {
            float4 v = ct4[i];
            acc += fabsf(v.x) + fabsf(v.y) + fabsf(v.z) + fabsf(v.w);
        }
        if (gtid == 0) {
            for (int i = nv4 << 2; i < n; i++) acc += fabsf(ct[i]);
        }
    }

    // Block reduction: warp shfl tree, then warp 0 folds 8 warp sums.
    acc = warp_reduce_sum(acc);
    if ((tid & 31) == 0) s_warp[tid >> 5] = acc;
    __syncthreads();

    if (tid == 0) {
        float v = s_warp[0];
        #pragma unroll
        for (int w = 1; w < RED_THREADS / 32; w++) v += s_warp[w];

        // Pack: fixed-point partial in bits [8:64), arrival count in [0:8).
        // |ct| >= 0 so the fixed value is non-negative; 128 arrivals < 256
        // so the count never carries into the sum field.
        unsigned long long contrib =
            (((unsigned long long)__float2ll_rn(v * FIX_SCALE)) << 8) | 1ull;

        unsigned long long old = atomicAdd(&g_acc, contrib);

        if ((old & 0xFFull) == (unsigned long long)(RED_BLOCKS - 1)) {
            // Last arrival: old + contrib is the complete packed total.
            unsigned long long total = (old + contrib) >> 8;
            out[0] = (float)((double)total) * FIX_INV * scale;
            g_acc = 0ull;  // restore for next graph replay
        }
    }
}

extern "C" void kernel_launch(void* const* d_in, const int* in_sizes, int n_in,
                              void* d_out, int out_size) {
    // Inputs (metadata order): pred_stage1 [1,C,H,W] f32, ct [1,H,W] f32,
    // target [1,1,H,W] i64. Only ct is needed (see identity above).
    const float* ct = (const float*)d_in[1];
    const int n = in_sizes[1];                      // H*W
    const int C = (n > 0) ? (in_sizes[0] / n) : 1;  // class count from pred size

    const double scale_d = (2.0 * (double)(C - 1)) /
                           ((double)C * (double)C * (double)n);
    const float scale = (float)scale_d;

    abs_mean_fused<<<RED_BLOCKS, RED_THREADS>>>(ct, n, scale, (float*)d_out);
}